// round 1
// baseline (speedup 1.0000x reference)
#include <cuda_runtime.h>
#include <math.h>

#define T_  2048
#define D_  768
#define L_  12
#define H_  12
#define DK_ 64
#define FF_ 2048
#define V_  50304
#define KC  4
#define EPSF 1e-6f

// ---------------- scratch (device globals; no runtime allocation) ----------------
__device__ float g_h  [T_*D_];
__device__ float g_x  [T_*D_];
__device__ float g_qp [T_*D_];
__device__ float g_kp [T_*D_];
__device__ float g_vp [T_*D_];
__device__ float g_q  [T_*D_];
__device__ float g_k  [T_*D_];
__device__ float g_v  [T_*D_];
__device__ float g_o  [T_*D_];
__device__ float g_y  [T_*D_];
__device__ float g_gate[T_*FF_];
__device__ float g_up  [T_*FF_];
__device__ float g_beta[T_*H_];
__device__ float g_loss, g_cnt;
__device__ float g_logits_fb[(size_t)T_*V_];   // fallback if d_out can't hold logits

// ---------------- kernels ----------------
__global__ void embed_k(const int* __restrict__ idx, const float* __restrict__ embed,
                        float* __restrict__ h) {
    int i = blockIdx.x * blockDim.x + threadIdx.x;
    if (i < T_ * D_) {
        int t = i / D_, d = i % D_;
        h[i] = embed[(size_t)idx[t] * D_ + d];
    }
}

// rmsnorm over D_, one block per row
__global__ void rmsnorm_k(const float* __restrict__ x, const float* __restrict__ w,
                          float* __restrict__ y) {
    int t = blockIdx.x;
    __shared__ float red[256];
    float ss = 0.f;
    for (int d = threadIdx.x; d < D_; d += 256) { float v = x[t*D_+d]; ss += v*v; }
    red[threadIdx.x] = ss; __syncthreads();
    for (int s = 128; s > 0; s >>= 1) {
        if (threadIdx.x < s) red[threadIdx.x] += red[threadIdx.x + s];
        __syncthreads();
    }
    float r = rsqrtf(red[0] / D_ + EPSF);
    for (int d = threadIdx.x; d < D_; d += 256) y[t*D_+d] = x[t*D_+d] * r * w[d];
}

// classic fp32 SGEMM: C[M,N] = A[M,K] @ B[K,N] (+C if accum). 128x128x8 tiles.
__global__ void sgemm_k(int M, int N, int K,
                        const float* __restrict__ A, const float* __restrict__ B,
                        float* __restrict__ C, int accum) {
    __shared__ float As[8][128];
    __shared__ float Bs[8][128];
    int tid = threadIdx.x;
    int row0 = blockIdx.y * 128, col0 = blockIdx.x * 128;
    int ty = tid / 16, tx = tid % 16;
    float acc[8][8];
    #pragma unroll
    for (int i = 0; i < 8; i++)
        #pragma unroll
        for (int j = 0; j < 8; j++) acc[i][j] = 0.f;

    int aRow = tid >> 1, aK = (tid & 1) * 4;
    int bK = tid >> 5,  bCol = (tid & 31) * 4;

    for (int k0 = 0; k0 < K; k0 += 8) {
        #pragma unroll
        for (int i = 0; i < 4; i++) {
            int gr = row0 + aRow, gk = k0 + aK + i;
            As[aK + i][aRow] = (gr < M && gk < K) ? A[(size_t)gr * K + gk] : 0.f;
        }
        #pragma unroll
        for (int i = 0; i < 4; i++) {
            int gk = k0 + bK, gc = col0 + bCol + i;
            Bs[bK][bCol + i] = (gk < K && gc < N) ? B[(size_t)gk * N + gc] : 0.f;
        }
        __syncthreads();
        #pragma unroll
        for (int kk = 0; kk < 8; kk++) {
            float a[8], b[8];
            #pragma unroll
            for (int i = 0; i < 8; i++) a[i] = As[kk][ty*8 + i];
            #pragma unroll
            for (int j = 0; j < 8; j++) b[j] = Bs[kk][tx*8 + j];
            #pragma unroll
            for (int i = 0; i < 8; i++)
                #pragma unroll
                for (int j = 0; j < 8; j++) acc[i][j] += a[i] * b[j];
        }
        __syncthreads();
    }
    #pragma unroll
    for (int i = 0; i < 8; i++) {
        int r = row0 + ty*8 + i;
        if (r >= M) continue;
        #pragma unroll
        for (int j = 0; j < 8; j++) {
            int c = col0 + tx*8 + j;
            if (c < N) {
                size_t o = (size_t)r * N + c;
                C[o] = accum ? (C[o] + acc[i][j]) : acc[i][j];
            }
        }
    }
}

// causal depthwise conv (K=4) + SiLU
__global__ void conv_silu_k(const float* __restrict__ x, const float* __restrict__ w,
                            float* __restrict__ y) {
    int i = blockIdx.x * blockDim.x + threadIdx.x;
    if (i >= T_ * D_) return;
    int t = i / D_, d = i % D_;
    float s = 0.f;
    #pragma unroll
    for (int j = 0; j < KC; j++) {
        int tt = t + j - (KC - 1);
        if (tt >= 0) s += x[tt*D_ + d] * w[d*KC + j];
    }
    y[i] = s / (1.f + expf(-s));
}

// l2norm over DK per (t,h); grid = T_*H_, block = 64
__global__ void l2norm_k(float* __restrict__ x) {
    int base = blockIdx.x * DK_;
    int tid = threadIdx.x;
    __shared__ float red[64];
    float v = x[base + tid];
    red[tid] = v * v; __syncthreads();
    for (int s = 32; s > 0; s >>= 1) {
        if (tid < s) red[tid] += red[tid + s];
        __syncthreads();
    }
    x[base + tid] = v * rsqrtf(red[0] + EPSF);
}

// per-head rmsnorm with weight w[DK]; grid = T_*H_, block = 64
__global__ void headrms_k(float* __restrict__ x, const float* __restrict__ w) {
    int base = blockIdx.x * DK_;
    int tid = threadIdx.x;
    __shared__ float red[64];
    float v = x[base + tid];
    red[tid] = v * v; __syncthreads();
    for (int s = 32; s > 0; s >>= 1) {
        if (tid < s) red[tid] += red[tid + s];
        __syncthreads();
    }
    x[base + tid] = v * rsqrtf(red[0] / DK_ + EPSF) * w[tid];
}

__global__ void sigmoid_k(float* __restrict__ x, int n) {
    int i = blockIdx.x * blockDim.x + threadIdx.x;
    if (i < n) x[i] = 1.f / (1.f + expf(-x[i]));
}

__global__ void silu_mul_k(float* __restrict__ g, const float* __restrict__ u, int n) {
    int i = blockIdx.x * blockDim.x + threadIdx.x;
    if (i < n) { float v = g[i]; g[i] = (v / (1.f + expf(-v))) * u[i]; }
}

// sequential delta rule; one block per head, 128 threads.
// Thread (vcol = tid&63, half = tid>>6) holds S[half*32 .. half*32+31][vcol] in regs.
__global__ void delta_k(const float* __restrict__ q, const float* __restrict__ k,
                        const float* __restrict__ v, const float* __restrict__ beta,
                        float* __restrict__ o) {
    int h = blockIdx.x;
    int tid = threadIdx.x;
    int vcol = tid & 63, rbase = (tid >> 6) * 32;
    float S[32];
    #pragma unroll
    for (int i = 0; i < 32; i++) S[i] = 0.f;
    __shared__ float ks[64], qs[64], vs[64], part[128];
    __shared__ float bs;

    for (int t = 0; t < T_; t++) {
        int off = (t * H_ + h) * DK_;
        if (tid < 64) { ks[tid] = k[off+tid]; qs[tid] = q[off+tid]; vs[tid] = v[off+tid]; }
        if (tid == 64) bs = beta[t * H_ + h];
        __syncthreads();                                  // (a) shared ready

        float a0 = 0.f, a1 = 0.f;
        #pragma unroll
        for (int i = 0; i < 32; i += 2) {
            a0 += ks[rbase+i]   * S[i];
            a1 += ks[rbase+i+1] * S[i+1];
        }
        part[tid] = a0 + a1; __syncthreads();             // (b)
        float kS = part[vcol] + part[vcol + 64];
        float dl = bs * (vs[vcol] - kS);
        __syncthreads();                                  // (c) all done reading part

        float o0 = 0.f, o1 = 0.f;
        #pragma unroll
        for (int i = 0; i < 32; i += 2) {
            S[i]   += ks[rbase+i]   * dl;  o0 += qs[rbase+i]   * S[i];
            S[i+1] += ks[rbase+i+1] * dl;  o1 += qs[rbase+i+1] * S[i+1];
        }
        part[tid] = o0 + o1; __syncthreads();             // (d)
        if (tid < 64) o[off + tid] = part[tid] + part[tid + 64];
    }
}

__global__ void zero_loss_k() { g_loss = 0.f; g_cnt = 0.f; }

// one block per row; two passes over V
__global__ void loss_k(const float* __restrict__ logits, const int* __restrict__ tgt) {
    int t = blockIdx.x;
    const float* row = logits + (size_t)t * V_;
    __shared__ float red[256];
    float m = -1e30f;
    for (int i = threadIdx.x; i < V_; i += 256) m = fmaxf(m, row[i]);
    red[threadIdx.x] = m; __syncthreads();
    for (int s = 128; s > 0; s >>= 1) {
        if (threadIdx.x < s) red[threadIdx.x] = fmaxf(red[threadIdx.x], red[threadIdx.x+s]);
        __syncthreads();
    }
    m = red[0]; __syncthreads();
    float sum = 0.f;
    for (int i = threadIdx.x; i < V_; i += 256) sum += expf(row[i] - m);
    red[threadIdx.x] = sum; __syncthreads();
    for (int s = 128; s > 0; s >>= 1) {
        if (threadIdx.x < s) red[threadIdx.x] += red[threadIdx.x+s];
        __syncthreads();
    }
    if (threadIdx.x == 0) {
        int tg = tgt[t];
        if (tg >= 0) {
            int tc = tg < 0 ? 0 : (tg > V_-1 ? V_-1 : tg);
            float lse = m + logf(red[0]);
            atomicAdd(&g_loss, lse - row[tc]);
            atomicAdd(&g_cnt, 1.f);
        }
    }
}

__global__ void finalize_k(float* __restrict__ out, long long out_size) {
    float loss = g_loss / fmaxf(g_cnt, 1.f);
    const long long LG = (long long)T_ * V_;
    if (out_size == LG + 1) out[LG] = loss;
    else if (out_size < LG) out[0] = loss;
}

// ---------------- host side ----------------
static void run_gemm(int M, int N, int K, const float* A, const float* B, float* C, int accum) {
    dim3 grid((N + 127) / 128, (M + 127) / 128);
    sgemm_k<<<grid, 256>>>(M, N, K, A, B, C, accum);
}

extern "C" void kernel_launch(void* const* d_in, const int* in_sizes, int n_in,
                              void* d_out, int out_size) {
    const int*   idx        = (const int*)  d_in[0];
    const int*   targets    = (const int*)  d_in[1];
    const float* embed      = (const float*)d_in[2];
    const float* Wq         = (const float*)d_in[3];
    const float* Wk         = (const float*)d_in[4];
    const float* Wv         = (const float*)d_in[5];
    const float* conv_q     = (const float*)d_in[6];
    const float* conv_k     = (const float*)d_in[7];
    const float* conv_v     = (const float*)d_in[8];
    const float* Wb         = (const float*)d_in[9];
    const float* o_norm_w   = (const float*)d_in[10];
    const float* Wo         = (const float*)d_in[11];
    const float* attn_norm  = (const float*)d_in[12];
    const float* mlp_norm   = (const float*)d_in[13];
    const float* Wgate      = (const float*)d_in[14];
    const float* Wup        = (const float*)d_in[15];
    const float* Wdown      = (const float*)d_in[16];
    const float* final_norm = (const float*)d_in[17];
    const float* lm_head    = (const float*)d_in[18];

    // resolve scratch symbols
    float *h, *x, *qp, *kp, *vp, *q, *k, *v, *o, *y, *gate, *up, *beta, *lfb;
    cudaGetSymbolAddress((void**)&h,    g_h);
    cudaGetSymbolAddress((void**)&x,    g_x);
    cudaGetSymbolAddress((void**)&qp,   g_qp);
    cudaGetSymbolAddress((void**)&kp,   g_kp);
    cudaGetSymbolAddress((void**)&vp,   g_vp);
    cudaGetSymbolAddress((void**)&q,    g_q);
    cudaGetSymbolAddress((void**)&k,    g_k);
    cudaGetSymbolAddress((void**)&v,    g_v);
    cudaGetSymbolAddress((void**)&o,    g_o);
    cudaGetSymbolAddress((void**)&y,    g_y);
    cudaGetSymbolAddress((void**)&gate, g_gate);
    cudaGetSymbolAddress((void**)&up,   g_up);
    cudaGetSymbolAddress((void**)&beta, g_beta);
    cudaGetSymbolAddress((void**)&lfb,  g_logits_fb);

    const long long LG = (long long)T_ * V_;
    float* logits = ((long long)out_size >= LG) ? (float*)d_out : lfb;

    const int TD = T_ * D_;
    const int TF = T_ * FF_;

    // embedding
    embed_k<<<(TD + 255) / 256, 256>>>(idx, embed, h);

    for (int l = 0; l < L_; l++) {
        const float* Wq_l = Wq + (size_t)l * D_ * D_;
        const float* Wk_l = Wk + (size_t)l * D_ * D_;
        const float* Wv_l = Wv + (size_t)l * D_ * D_;
        const float* Wo_l = Wo + (size_t)l * D_ * D_;
        const float* Wb_l = Wb + (size_t)l * D_ * H_;
        const float* cq_l = conv_q + (size_t)l * D_ * KC;
        const float* ck_l = conv_k + (size_t)l * D_ * KC;
        const float* cv_l = conv_v + (size_t)l * D_ * KC;
        const float* Wg_l = Wgate + (size_t)l * D_ * FF_;
        const float* Wu_l = Wup   + (size_t)l * D_ * FF_;
        const float* Wd_l = Wdown + (size_t)l * FF_ * D_;

        // attn pre-norm
        rmsnorm_k<<<T_, 256>>>(h, attn_norm + (size_t)l * D_, x);

        // projections
        run_gemm(T_, D_, D_, x, Wq_l, qp, 0);
        run_gemm(T_, D_, D_, x, Wk_l, kp, 0);
        run_gemm(T_, D_, D_, x, Wv_l, vp, 0);
        run_gemm(T_, H_, D_, x, Wb_l, beta, 0);
        sigmoid_k<<<(T_*H_ + 255) / 256, 256>>>(beta, T_*H_);

        // conv + silu
        conv_silu_k<<<(TD + 255) / 256, 256>>>(qp, cq_l, q);
        conv_silu_k<<<(TD + 255) / 256, 256>>>(kp, ck_l, k);
        conv_silu_k<<<(TD + 255) / 256, 256>>>(vp, cv_l, v);

        // per-head l2 norms on q,k
        l2norm_k<<<T_*H_, 64>>>(q);
        l2norm_k<<<T_*H_, 64>>>(k);

        // delta rule recurrence
        delta_k<<<H_, 128>>>(q, k, v, beta, o);

        // per-head output rmsnorm
        headrms_k<<<T_*H_, 64>>>(o, o_norm_w + (size_t)l * DK_);

        // residual: h += o @ Wo
        run_gemm(T_, D_, D_, o, Wo_l, h, 1);

        // MLP
        rmsnorm_k<<<T_, 256>>>(h, mlp_norm + (size_t)l * D_, y);
        run_gemm(T_, FF_, D_, y, Wg_l, gate, 0);
        run_gemm(T_, FF_, D_, y, Wu_l, up, 0);
        silu_mul_k<<<(TF + 255) / 256, 256>>>(gate, up, TF);
        run_gemm(T_, D_, FF_, gate, Wd_l, h, 1);
    }

    // final norm + lm head
    rmsnorm_k<<<T_, 256>>>(h, final_norm, y);
    run_gemm(T_, V_, D_, y, lm_head, logits, 0);

    // loss
    zero_loss_k<<<1, 1>>>();
    loss_k<<<T_, 256>>>(logits, targets);
    finalize_k<<<1, 1>>>((float*)d_out, (long long)out_size);
}

// round 5
// speedup vs baseline: 1.3087x; 1.3087x over previous
#include <cuda_runtime.h>
#include <stdint.h>
#include <math.h>

#define T_  2048
#define D_  768
#define L_  12
#define H_  12
#define DK_ 64
#define FF_ 2048
#define V_  50304
#define KC  4
#define EPSF 1e-6f

// ---------------- scratch (device globals; no runtime allocation) ----------------
__device__ float g_h  [T_*D_];
__device__ float g_x  [T_*D_];
__device__ float g_qp [T_*D_];
__device__ float g_kp [T_*D_];
__device__ float g_vp [T_*D_];
__device__ float g_q  [T_*D_];
__device__ float g_k  [T_*D_];
__device__ float g_v  [T_*D_];
__device__ float g_o  [T_*D_];
__device__ float g_y  [T_*D_];
__device__ float g_gate[T_*FF_];
__device__ float g_up  [T_*FF_];
__device__ float g_beta[T_*H_];
__device__ float g_loss, g_cnt;
__device__ float g_logits_fb[(size_t)T_*V_];

// ---------------- small kernels ----------------
__global__ void embed_k(const int* __restrict__ idx, const float* __restrict__ embed,
                        float* __restrict__ h) {
    int i = blockIdx.x * blockDim.x + threadIdx.x;
    if (i < T_ * D_) {
        int t = i / D_, d = i % D_;
        h[i] = embed[(size_t)idx[t] * D_ + d];
    }
}

__global__ void rmsnorm_k(const float* __restrict__ x, const float* __restrict__ w,
                          float* __restrict__ y) {
    int t = blockIdx.x;
    __shared__ float red[256];
    float ss = 0.f;
    for (int d = threadIdx.x; d < D_; d += 256) { float v = x[t*D_+d]; ss += v*v; }
    red[threadIdx.x] = ss; __syncthreads();
    for (int s = 128; s > 0; s >>= 1) {
        if (threadIdx.x < s) red[threadIdx.x] += red[threadIdx.x + s];
        __syncthreads();
    }
    float r = rsqrtf(red[0] / D_ + EPSF);
    for (int d = threadIdx.x; d < D_; d += 256) y[t*D_+d] = x[t*D_+d] * r * w[d];
}

// fallback fp32 SGEMM (only for tiny N, e.g. beta N=12)
__global__ void sgemm_k(int M, int N, int K,
                        const float* __restrict__ A, const float* __restrict__ B,
                        float* __restrict__ C, int accum) {
    __shared__ float As[8][128];
    __shared__ float Bs[8][128];
    int tid = threadIdx.x;
    int row0 = blockIdx.y * 128, col0 = blockIdx.x * 128;
    int ty = tid / 16, tx = tid % 16;
    float acc[8][8];
    #pragma unroll
    for (int i = 0; i < 8; i++)
        #pragma unroll
        for (int j = 0; j < 8; j++) acc[i][j] = 0.f;
    int aRow = tid >> 1, aK = (tid & 1) * 4;
    int bK = tid >> 5,  bCol = (tid & 31) * 4;
    for (int k0 = 0; k0 < K; k0 += 8) {
        #pragma unroll
        for (int i = 0; i < 4; i++) {
            int gr = row0 + aRow, gk = k0 + aK + i;
            As[aK + i][aRow] = (gr < M && gk < K) ? A[(size_t)gr * K + gk] : 0.f;
        }
        #pragma unroll
        for (int i = 0; i < 4; i++) {
            int gk = k0 + bK, gc = col0 + bCol + i;
            Bs[bK][bCol + i] = (gk < K && gc < N) ? B[(size_t)gk * N + gc] : 0.f;
        }
        __syncthreads();
        #pragma unroll
        for (int kk = 0; kk < 8; kk++) {
            float a[8], b[8];
            #pragma unroll
            for (int i = 0; i < 8; i++) a[i] = As[kk][ty*8 + i];
            #pragma unroll
            for (int j = 0; j < 8; j++) b[j] = Bs[kk][tx*8 + j];
            #pragma unroll
            for (int i = 0; i < 8; i++)
                #pragma unroll
                for (int j = 0; j < 8; j++) acc[i][j] += a[i] * b[j];
        }
        __syncthreads();
    }
    #pragma unroll
    for (int i = 0; i < 8; i++) {
        int r = row0 + ty*8 + i;
        if (r >= M) continue;
        #pragma unroll
        for (int j = 0; j < 8; j++) {
            int c = col0 + tx*8 + j;
            if (c < N) {
                size_t o = (size_t)r * N + c;
                C[o] = accum ? (C[o] + acc[i][j]) : acc[i][j];
            }
        }
    }
}

// ---------------- split-tf32 tensor-core GEMM (3xTF32, near-fp32 accuracy) ----
// C[M,N] = A[M,K] @ B[K,N] (+C). Requires M%128==0, N%128==0, K%16==0.
// 256 threads = 8 warps; warp tile 32x64 of m16n8k8 mma.
__device__ __forceinline__ unsigned int f2tf32(float f) {
    unsigned int r;
    asm("cvt.rna.tf32.f32 %0, %1;" : "=r"(r) : "f"(f));
    return r;
}
__device__ __forceinline__ void split_tf32(float f, unsigned int& hi, unsigned int& lo) {
    hi = f2tf32(f);
    lo = f2tf32(f - __uint_as_float(hi));
}

#define MMA_TF32(acc, a0,a1,a2,a3, b0,b1)                                     \
    asm volatile(                                                             \
        "mma.sync.aligned.m16n8k8.row.col.f32.tf32.tf32.f32 "                 \
        "{%0,%1,%2,%3}, {%4,%5,%6,%7}, {%8,%9}, {%0,%1,%2,%3};\n"             \
        : "+f"(acc[0]), "+f"(acc[1]), "+f"(acc[2]), "+f"(acc[3])              \
        : "r"(a0), "r"(a1), "r"(a2), "r"(a3), "r"(b0), "r"(b1))

__global__ __launch_bounds__(256)
void tf32gemm_k(int M, int N, int K,
                const float* __restrict__ A, const float* __restrict__ B,
                float* __restrict__ C, int accum) {
    __shared__ unsigned int AsH[128][20];   // [row][k] pad-20: conflict-free frags
    __shared__ unsigned int AsL[128][20];
    __shared__ unsigned int BsH[16][132];   // [k][col]
    __shared__ unsigned int BsL[16][132];

    int tid = threadIdx.x;
    int lane = tid & 31, warp = tid >> 5;
    int warpM = warp & 3, warpN = warp >> 2;    // 4 x 2 warps
    int gid = lane >> 2, tig = lane & 3;

    int row0 = blockIdx.y * 128, col0 = blockIdx.x * 128;

    float acc[2][8][4];
    #pragma unroll
    for (int mt = 0; mt < 2; mt++)
        #pragma unroll
        for (int nt = 0; nt < 8; nt++)
            #pragma unroll
            for (int i = 0; i < 4; i++) acc[mt][nt][i] = 0.f;

    int aRow = tid >> 1, aKq = (tid & 1) * 8;
    int bK = tid >> 4, bNq = (tid & 15) * 8;

    for (int k0 = 0; k0 < K; k0 += 16) {
        // load A 128x16 (split hi/lo)
        {
            const float4* src = (const float4*)(A + (size_t)(row0 + aRow) * K + k0 + aKq);
            float4 v0 = src[0], v1 = src[1];
            unsigned int* dh = &AsH[aRow][aKq];
            unsigned int* dl = &AsL[aRow][aKq];
            split_tf32(v0.x, dh[0], dl[0]); split_tf32(v0.y, dh[1], dl[1]);
            split_tf32(v0.z, dh[2], dl[2]); split_tf32(v0.w, dh[3], dl[3]);
            split_tf32(v1.x, dh[4], dl[4]); split_tf32(v1.y, dh[5], dl[5]);
            split_tf32(v1.z, dh[6], dl[6]); split_tf32(v1.w, dh[7], dl[7]);
        }
        // load B 16x128 (split hi/lo)
        {
            const float4* src = (const float4*)(B + (size_t)(k0 + bK) * N + col0 + bNq);
            float4 v0 = src[0], v1 = src[1];
            unsigned int* dh = &BsH[bK][bNq];
            unsigned int* dl = &BsL[bK][bNq];
            split_tf32(v0.x, dh[0], dl[0]); split_tf32(v0.y, dh[1], dl[1]);
            split_tf32(v0.z, dh[2], dl[2]); split_tf32(v0.w, dh[3], dl[3]);
            split_tf32(v1.x, dh[4], dl[4]); split_tf32(v1.y, dh[5], dl[5]);
            split_tf32(v1.z, dh[6], dl[6]); split_tf32(v1.w, dh[7], dl[7]);
        }
        __syncthreads();

        #pragma unroll
        for (int ks = 0; ks < 2; ks++) {
            unsigned int afH[2][4], afL[2][4];
            #pragma unroll
            for (int mt = 0; mt < 2; mt++) {
                int r = warpM * 32 + mt * 16 + gid;
                int c = ks * 8 + tig;
                afH[mt][0] = AsH[r][c];     afL[mt][0] = AsL[r][c];
                afH[mt][1] = AsH[r + 8][c]; afL[mt][1] = AsL[r + 8][c];
                afH[mt][2] = AsH[r][c + 4]; afL[mt][2] = AsL[r][c + 4];
                afH[mt][3] = AsH[r + 8][c + 4]; afL[mt][3] = AsL[r + 8][c + 4];
            }
            unsigned int bfH[8][2], bfL[8][2];
            #pragma unroll
            for (int nt = 0; nt < 8; nt++) {
                int n = warpN * 64 + nt * 8 + gid;
                int kk = ks * 8 + tig;
                bfH[nt][0] = BsH[kk][n];     bfL[nt][0] = BsL[kk][n];
                bfH[nt][1] = BsH[kk + 4][n]; bfL[nt][1] = BsL[kk + 4][n];
            }
            #pragma unroll
            for (int mt = 0; mt < 2; mt++)
                #pragma unroll
                for (int nt = 0; nt < 8; nt++) {
                    // hi*lo + lo*hi first (small terms), hi*hi last
                    MMA_TF32(acc[mt][nt], afH[mt][0], afH[mt][1], afH[mt][2], afH[mt][3],
                             bfL[nt][0], bfL[nt][1]);
                    MMA_TF32(acc[mt][nt], afL[mt][0], afL[mt][1], afL[mt][2], afL[mt][3],
                             bfH[nt][0], bfH[nt][1]);
                    MMA_TF32(acc[mt][nt], afH[mt][0], afH[mt][1], afH[mt][2], afH[mt][3],
                             bfH[nt][0], bfH[nt][1]);
                }
        }
        __syncthreads();
    }

    // epilogue
    #pragma unroll
    for (int mt = 0; mt < 2; mt++) {
        int r = row0 + warpM * 32 + mt * 16 + gid;
        #pragma unroll
        for (int nt = 0; nt < 8; nt++) {
            int c = col0 + warpN * 64 + nt * 8 + tig * 2;
            float* p0 = C + (size_t)r * N + c;
            float* p1 = C + (size_t)(r + 8) * N + c;
            if (accum) {
                p0[0] += acc[mt][nt][0]; p0[1] += acc[mt][nt][1];
                p1[0] += acc[mt][nt][2]; p1[1] += acc[mt][nt][3];
            } else {
                p0[0] = acc[mt][nt][0]; p0[1] = acc[mt][nt][1];
                p1[0] = acc[mt][nt][2]; p1[1] = acc[mt][nt][3];
            }
        }
    }
}

// ---------------- elementwise ----------------
__global__ void conv_silu_k(const float* __restrict__ x, const float* __restrict__ w,
                            float* __restrict__ y) {
    int i = blockIdx.x * blockDim.x + threadIdx.x;
    if (i >= T_ * D_) return;
    int t = i / D_, d = i % D_;
    float s = 0.f;
    #pragma unroll
    for (int j = 0; j < KC; j++) {
        int tt = t + j - (KC - 1);
        if (tt >= 0) s += x[tt*D_ + d] * w[d*KC + j];
    }
    y[i] = s / (1.f + expf(-s));
}

__global__ void l2norm_k(float* __restrict__ x) {
    int base = blockIdx.x * DK_;
    int tid = threadIdx.x;
    __shared__ float red[64];
    float v = x[base + tid];
    red[tid] = v * v; __syncthreads();
    for (int s = 32; s > 0; s >>= 1) {
        if (tid < s) red[tid] += red[tid + s];
        __syncthreads();
    }
    x[base + tid] = v * rsqrtf(red[0] + EPSF);
}

__global__ void headrms_k(float* __restrict__ x, const float* __restrict__ w) {
    int base = blockIdx.x * DK_;
    int tid = threadIdx.x;
    __shared__ float red[64];
    float v = x[base + tid];
    red[tid] = v * v; __syncthreads();
    for (int s = 32; s > 0; s >>= 1) {
        if (tid < s) red[tid] += red[tid + s];
        __syncthreads();
    }
    x[base + tid] = v * rsqrtf(red[0] / DK_ + EPSF) * w[tid];
}

__global__ void sigmoid_k(float* __restrict__ x, int n) {
    int i = blockIdx.x * blockDim.x + threadIdx.x;
    if (i < n) x[i] = 1.f / (1.f + expf(-x[i]));
}

__global__ void silu_mul_k(float* __restrict__ g, const float* __restrict__ u, int n) {
    int i = blockIdx.x * blockDim.x + threadIdx.x;
    if (i < n) { float v = g[i]; g[i] = (v / (1.f + expf(-v))) * u[i]; }
}

// ---------------- delta rule ----------------
__global__ void delta_k(const float* __restrict__ q, const float* __restrict__ k,
                        const float* __restrict__ v, const float* __restrict__ beta,
                        float* __restrict__ o) {
    int h = blockIdx.x;
    int tid = threadIdx.x;
    int vcol = tid >> 1, rbase = (tid & 1) * 32;
    float S[32];
    #pragma unroll
    for (int i = 0; i < 32; i++) S[i] = 0.f;
    __shared__ float ks[2][64], qs[2][64], vs[2][64], bsh[2];

    for (int t = 0; t < T_; t++) {
        int buf = t & 1;
        int off = (t * H_ + h) * DK_;
        if (tid < 64) { ks[buf][tid] = k[off+tid]; qs[buf][tid] = q[off+tid]; }
        else          { vs[buf][tid-64] = v[off+tid-64]; }
        if (tid == 127) bsh[buf] = beta[t * H_ + h];
        __syncthreads();

        const float* kk = ks[buf];
        const float* qq = qs[buf];
        float a0 = 0.f, a1 = 0.f;
        #pragma unroll
        for (int i = 0; i < 32; i += 2) {
            a0 += kk[rbase+i]   * S[i];
            a1 += kk[rbase+i+1] * S[i+1];
        }
        float part = a0 + a1;
        float kS = part + __shfl_xor_sync(0xffffffffu, part, 1);
        float dl = bsh[buf] * (vs[buf][vcol] - kS);

        float o0 = 0.f, o1 = 0.f;
        #pragma unroll
        for (int i = 0; i < 32; i += 2) {
            S[i]   += kk[rbase+i]   * dl;  o0 += qq[rbase+i]   * S[i];
            S[i+1] += kk[rbase+i+1] * dl;  o1 += qq[rbase+i+1] * S[i+1];
        }
        float op = o0 + o1;
        float ov = op + __shfl_xor_sync(0xffffffffu, op, 1);
        if ((tid & 1) == 0) o[off + vcol] = ov;
    }
}

__global__ void zero_loss_k() { g_loss = 0.f; g_cnt = 0.f; }

__global__ void loss_k(const float* __restrict__ logits, const int* __restrict__ tgt) {
    int t = blockIdx.x;
    const float* row = logits + (size_t)t * V_;
    __shared__ float red[256];
    float m = -1e30f;
    for (int i = threadIdx.x; i < V_; i += 256) m = fmaxf(m, row[i]);
    red[threadIdx.x] = m; __syncthreads();
    for (int s = 128; s > 0; s >>= 1) {
        if (threadIdx.x < s) red[threadIdx.x] = fmaxf(red[threadIdx.x], red[threadIdx.x+s]);
        __syncthreads();
    }
    m = red[0]; __syncthreads();
    float sum = 0.f;
    for (int i = threadIdx.x; i < V_; i += 256) sum += expf(row[i] - m);
    red[threadIdx.x] = sum; __syncthreads();
    for (int s = 128; s > 0; s >>= 1) {
        if (threadIdx.x < s) red[threadIdx.x] += red[threadIdx.x+s];
        __syncthreads();
    }
    if (threadIdx.x == 0) {
        int tg = tgt[t];
        if (tg >= 0) {
            int tc = tg < 0 ? 0 : (tg > V_-1 ? V_-1 : tg);
            float lse = m + logf(red[0]);
            atomicAdd(&g_loss, lse - row[tc]);
            atomicAdd(&g_cnt, 1.f);
        }
    }
}

__global__ void finalize_k(float* __restrict__ out, long long out_size) {
    float loss = g_loss / fmaxf(g_cnt, 1.f);
    const long long LG = (long long)T_ * V_;
    if (out_size == LG + 1) out[LG] = loss;
    else if (out_size < LG) out[0] = loss;
}

// ---------------- host side ----------------
static void run_gemm(int M, int N, int K, const float* A, const float* B, float* C, int accum) {
    if ((M % 128 == 0) && (N % 128 == 0) && (K % 16 == 0)) {
        dim3 grid(N / 128, M / 128);
        tf32gemm_k<<<grid, 256>>>(M, N, K, A, B, C, accum);
    } else {
        dim3 grid((N + 127) / 128, (M + 127) / 128);
        sgemm_k<<<grid, 256>>>(M, N, K, A, B, C, accum);
    }
}

extern "C" void kernel_launch(void* const* d_in, const int* in_sizes, int n_in,
                              void* d_out, int out_size) {
    const int*   idx        = (const int*)  d_in[0];
    const int*   targets    = (const int*)  d_in[1];
    const float* embed      = (const float*)d_in[2];
    const float* Wq         = (const float*)d_in[3];
    const float* Wk         = (const float*)d_in[4];
    const float* Wv         = (const float*)d_in[5];
    const float* conv_q     = (const float*)d_in[6];
    const float* conv_k     = (const float*)d_in[7];
    const float* conv_v     = (const float*)d_in[8];
    const float* Wb         = (const float*)d_in[9];
    const float* o_norm_w   = (const float*)d_in[10];
    const float* Wo         = (const float*)d_in[11];
    const float* attn_norm  = (const float*)d_in[12];
    const float* mlp_norm   = (const float*)d_in[13];
    const float* Wgate      = (const float*)d_in[14];
    const float* Wup        = (const float*)d_in[15];
    const float* Wdown      = (const float*)d_in[16];
    const float* final_norm = (const float*)d_in[17];
    const float* lm_head    = (const float*)d_in[18];

    float *h, *x, *qp, *kp, *vp, *q, *k, *v, *o, *y, *gate, *up, *beta, *lfb;
    cudaGetSymbolAddress((void**)&h,    g_h);
    cudaGetSymbolAddress((void**)&x,    g_x);
    cudaGetSymbolAddress((void**)&qp,   g_qp);
    cudaGetSymbolAddress((void**)&kp,   g_kp);
    cudaGetSymbolAddress((void**)&vp,   g_vp);
    cudaGetSymbolAddress((void**)&q,    g_q);
    cudaGetSymbolAddress((void**)&k,    g_k);
    cudaGetSymbolAddress((void**)&v,    g_v);
    cudaGetSymbolAddress((void**)&o,    g_o);
    cudaGetSymbolAddress((void**)&y,    g_y);
    cudaGetSymbolAddress((void**)&gate, g_gate);
    cudaGetSymbolAddress((void**)&up,   g_up);
    cudaGetSymbolAddress((void**)&beta, g_beta);
    cudaGetSymbolAddress((void**)&lfb,  g_logits_fb);

    const long long LG = (long long)T_ * V_;
    float* logits = ((long long)out_size >= LG) ? (float*)d_out : lfb;

    const int TD = T_ * D_;
    const int TF = T_ * FF_;

    embed_k<<<(TD + 255) / 256, 256>>>(idx, embed, h);

    for (int l = 0; l < L_; l++) {
        const float* Wq_l = Wq + (size_t)l * D_ * D_;
        const float* Wk_l = Wk + (size_t)l * D_ * D_;
        const float* Wv_l = Wv + (size_t)l * D_ * D_;
        const float* Wo_l = Wo + (size_t)l * D_ * D_;
        const float* Wb_l = Wb + (size_t)l * D_ * H_;
        const float* cq_l = conv_q + (size_t)l * D_ * KC;
        const float* ck_l = conv_k + (size_t)l * D_ * KC;
        const float* cv_l = conv_v + (size_t)l * D_ * KC;
        const float* Wg_l = Wgate + (size_t)l * D_ * FF_;
        const float* Wu_l = Wup   + (size_t)l * D_ * FF_;
        const float* Wd_l = Wdown + (size_t)l * FF_ * D_;

        rmsnorm_k<<<T_, 256>>>(h, attn_norm + (size_t)l * D_, x);

        run_gemm(T_, D_, D_, x, Wq_l, qp, 0);
        run_gemm(T_, D_, D_, x, Wk_l, kp, 0);
        run_gemm(T_, D_, D_, x, Wv_l, vp, 0);
        run_gemm(T_, H_, D_, x, Wb_l, beta, 0);
        sigmoid_k<<<(T_*H_ + 255) / 256, 256>>>(beta, T_*H_);

        conv_silu_k<<<(TD + 255) / 256, 256>>>(qp, cq_l, q);
        conv_silu_k<<<(TD + 255) / 256, 256>>>(kp, ck_l, k);
        conv_silu_k<<<(TD + 255) / 256, 256>>>(vp, cv_l, v);

        l2norm_k<<<T_*H_, 64>>>(q);
        l2norm_k<<<T_*H_, 64>>>(k);

        delta_k<<<H_, 128>>>(q, k, v, beta, o);

        headrms_k<<<T_*H_, 64>>>(o, o_norm_w + (size_t)l * DK_);

        run_gemm(T_, D_, D_, o, Wo_l, h, 1);

        rmsnorm_k<<<T_, 256>>>(h, mlp_norm + (size_t)l * D_, y);
        run_gemm(T_, FF_, D_, y, Wg_l, gate, 0);
        run_gemm(T_, FF_, D_, y, Wu_l, up, 0);
        silu_mul_k<<<(TF + 255) / 256, 256>>>(gate, up, TF);
        run_gemm(T_, D_, FF_, gate, Wd_l, h, 1);
    }

    rmsnorm_k<<<T_, 256>>>(h, final_norm, y);
    run_gemm(T_, V_, D_, y, lm_head, logits, 0);

    zero_loss_k<<<1, 1>>>();
    loss_k<<<T_, 256>>>(logits, targets);
    finalize_k<<<1, 1>>>((float*)d_out, (long long)out_size);
}

// round 6
// speedup vs baseline: 1.6055x; 1.2268x over previous
#include <cuda_runtime.h>
#include <stdint.h>
#include <math.h>

#define T_  2048
#define D_  768
#define L_  12
#define H_  12
#define DK_ 64
#define FF_ 2048
#define V_  50304
#define KC  4
#define EPSF 1e-6f

// ---------------- scratch (device globals; no runtime allocation) ----------------
__device__ float g_h  [T_*D_];
__device__ float g_x  [T_*D_];
__device__ float g_qp [T_*D_];
__device__ float g_kp [T_*D_];
__device__ float g_vp [T_*D_];
__device__ float g_q  [T_*D_];
__device__ float g_k  [T_*D_];
__device__ float g_v  [T_*D_];
__device__ float g_o  [T_*D_];
__device__ float g_y  [T_*D_];
__device__ float g_gate[T_*FF_];
__device__ float g_up  [T_*FF_];
__device__ float g_beta[T_*H_];
__device__ float g_loss, g_cnt;
__device__ float g_logits_fb[(size_t)T_*V_];

// ---------------- small kernels ----------------
__global__ void embed_k(const int* __restrict__ idx, const float* __restrict__ embed,
                        float* __restrict__ h) {
    int i = blockIdx.x * blockDim.x + threadIdx.x;
    if (i < T_ * D_) {
        int t = i / D_, d = i % D_;
        h[i] = embed[(size_t)idx[t] * D_ + d];
    }
}

__global__ void rmsnorm_k(const float* __restrict__ x, const float* __restrict__ w,
                          float* __restrict__ y) {
    int t = blockIdx.x;
    __shared__ float red[256];
    float ss = 0.f;
    for (int d = threadIdx.x; d < D_; d += 256) { float v = x[t*D_+d]; ss += v*v; }
    red[threadIdx.x] = ss; __syncthreads();
    for (int s = 128; s > 0; s >>= 1) {
        if (threadIdx.x < s) red[threadIdx.x] += red[threadIdx.x + s];
        __syncthreads();
    }
    float r = rsqrtf(red[0] / D_ + EPSF);
    for (int d = threadIdx.x; d < D_; d += 256) y[t*D_+d] = x[t*D_+d] * r * w[d];
}

// fallback fp32 SGEMM (only for tiny N, e.g. beta N=12)
__global__ void sgemm_k(int M, int N, int K,
                        const float* __restrict__ A, const float* __restrict__ B,
                        float* __restrict__ C, int accum) {
    __shared__ float As[8][128];
    __shared__ float Bs[8][128];
    int tid = threadIdx.x;
    int row0 = blockIdx.y * 128, col0 = blockIdx.x * 128;
    int ty = tid / 16, tx = tid % 16;
    float acc[8][8];
    #pragma unroll
    for (int i = 0; i < 8; i++)
        #pragma unroll
        for (int j = 0; j < 8; j++) acc[i][j] = 0.f;
    int aRow = tid >> 1, aK = (tid & 1) * 4;
    int bK = tid >> 5,  bCol = (tid & 31) * 4;
    for (int k0 = 0; k0 < K; k0 += 8) {
        #pragma unroll
        for (int i = 0; i < 4; i++) {
            int gr = row0 + aRow, gk = k0 + aK + i;
            As[aK + i][aRow] = (gr < M && gk < K) ? A[(size_t)gr * K + gk] : 0.f;
        }
        #pragma unroll
        for (int i = 0; i < 4; i++) {
            int gk = k0 + bK, gc = col0 + bCol + i;
            Bs[bK][bCol + i] = (gk < K && gc < N) ? B[(size_t)gk * N + gc] : 0.f;
        }
        __syncthreads();
        #pragma unroll
        for (int kk = 0; kk < 8; kk++) {
            float a[8], b[8];
            #pragma unroll
            for (int i = 0; i < 8; i++) a[i] = As[kk][ty*8 + i];
            #pragma unroll
            for (int j = 0; j < 8; j++) b[j] = Bs[kk][tx*8 + j];
            #pragma unroll
            for (int i = 0; i < 8; i++)
                #pragma unroll
                for (int j = 0; j < 8; j++) acc[i][j] += a[i] * b[j];
        }
        __syncthreads();
    }
    #pragma unroll
    for (int i = 0; i < 8; i++) {
        int r = row0 + ty*8 + i;
        if (r >= M) continue;
        #pragma unroll
        for (int j = 0; j < 8; j++) {
            int c = col0 + tx*8 + j;
            if (c < N) {
                size_t o = (size_t)r * N + c;
                C[o] = accum ? (C[o] + acc[i][j]) : acc[i][j];
            }
        }
    }
}

// ---------------- split-tf32 tensor-core GEMM (3xTF32, near-fp32 accuracy) ----
// C[M,N] = A[M,K] @ B[K,N] (+C). Requires M%64==0, N%128==0, K%16==0.
// Tile 64x128x16; 256 threads = 8 warps (2 x 4), warp tile 32x32.
// Register-prefetch double buffering of global loads.
__device__ __forceinline__ unsigned int f2tf32(float f) {
    unsigned int r;
    asm("cvt.rna.tf32.f32 %0, %1;" : "=r"(r) : "f"(f));
    return r;
}
__device__ __forceinline__ void split_tf32(float f, unsigned int& hi, unsigned int& lo) {
    hi = f2tf32(f);
    lo = f2tf32(f - __uint_as_float(hi));
}

#define MMA_TF32(acc, a0,a1,a2,a3, b0,b1)                                     \
    asm volatile(                                                             \
        "mma.sync.aligned.m16n8k8.row.col.f32.tf32.tf32.f32 "                 \
        "{%0,%1,%2,%3}, {%4,%5,%6,%7}, {%8,%9}, {%0,%1,%2,%3};\n"             \
        : "+f"(acc[0]), "+f"(acc[1]), "+f"(acc[2]), "+f"(acc[3])              \
        : "r"(a0), "r"(a1), "r"(a2), "r"(a3), "r"(b0), "r"(b1))

__global__ __launch_bounds__(256, 2)
void tf32gemm_k(int M, int N, int K,
                const float* __restrict__ A, const float* __restrict__ B,
                float* __restrict__ C, int accum) {
    __shared__ unsigned int AsH[64][20];    // [row][k], pad 20: conflict-free frags
    __shared__ unsigned int AsL[64][20];
    __shared__ unsigned int BsH[16][136];   // [k][col], pad 136: 16B-aligned rows
    __shared__ unsigned int BsL[16][136];

    int tid = threadIdx.x;
    int lane = tid & 31, warp = tid >> 5;
    int warpM = warp & 1, warpN = warp >> 1;    // 2 x 4 warps
    int gid = lane >> 2, tig = lane & 3;

    int row0 = blockIdx.y * 64, col0 = blockIdx.x * 128;

    float acc[2][4][4];
    #pragma unroll
    for (int mt = 0; mt < 2; mt++)
        #pragma unroll
        for (int nt = 0; nt < 4; nt++)
            #pragma unroll
            for (int i = 0; i < 4; i++) acc[mt][nt][i] = 0.f;

    // A loader: 64x16 tile, 4 floats/thread: row = tid/4, k-offset = (tid%4)*4
    int aRow = tid >> 2, aKq = (tid & 3) * 4;
    // B loader: 16x128 tile, 8 floats/thread: k = tid/16, n-offset = (tid%16)*8
    int bK = tid >> 4, bNq = (tid & 15) * 8;

    const float* aPtr = A + (size_t)(row0 + aRow) * K + aKq;
    const float* bPtr = B + (size_t)bK * N + col0 + bNq;

    int KT = K / 16;

    // prefetch tile 0
    float4 apf = *(const float4*)aPtr;
    float4 bpf0 = ((const float4*)bPtr)[0];
    float4 bpf1 = ((const float4*)bPtr)[1];

    for (int kt = 0; kt < KT; kt++) {
        // convert + store prefetched tile to smem (hi/lo)
        {
            unsigned int h0,h1,h2,h3, l0,l1,l2,l3;
            split_tf32(apf.x, h0, l0); split_tf32(apf.y, h1, l1);
            split_tf32(apf.z, h2, l2); split_tf32(apf.w, h3, l3);
            *(uint4*)&AsH[aRow][aKq] = make_uint4(h0,h1,h2,h3);
            *(uint4*)&AsL[aRow][aKq] = make_uint4(l0,l1,l2,l3);
            split_tf32(bpf0.x, h0, l0); split_tf32(bpf0.y, h1, l1);
            split_tf32(bpf0.z, h2, l2); split_tf32(bpf0.w, h3, l3);
            *(uint4*)&BsH[bK][bNq] = make_uint4(h0,h1,h2,h3);
            *(uint4*)&BsL[bK][bNq] = make_uint4(l0,l1,l2,l3);
            split_tf32(bpf1.x, h0, l0); split_tf32(bpf1.y, h1, l1);
            split_tf32(bpf1.z, h2, l2); split_tf32(bpf1.w, h3, l3);
            *(uint4*)&BsH[bK][bNq + 4] = make_uint4(h0,h1,h2,h3);
            *(uint4*)&BsL[bK][bNq + 4] = make_uint4(l0,l1,l2,l3);
        }
        __syncthreads();

        // issue next tile's global loads (overlap with mma below)
        if (kt + 1 < KT) {
            int k0 = (kt + 1) * 16;
            apf  = *(const float4*)(aPtr + k0);
            const float* bp = bPtr + (size_t)k0 * N;
            bpf0 = ((const float4*)bp)[0];
            bpf1 = ((const float4*)bp)[1];
        }

        #pragma unroll
        for (int ks = 0; ks < 2; ks++) {
            unsigned int afH[2][4], afL[2][4];
            #pragma unroll
            for (int mt = 0; mt < 2; mt++) {
                int r = warpM * 32 + mt * 16 + gid;
                int c = ks * 8 + tig;
                afH[mt][0] = AsH[r][c];         afL[mt][0] = AsL[r][c];
                afH[mt][1] = AsH[r + 8][c];     afL[mt][1] = AsL[r + 8][c];
                afH[mt][2] = AsH[r][c + 4];     afL[mt][2] = AsL[r][c + 4];
                afH[mt][3] = AsH[r + 8][c + 4]; afL[mt][3] = AsL[r + 8][c + 4];
            }
            unsigned int bfH[4][2], bfL[4][2];
            #pragma unroll
            for (int nt = 0; nt < 4; nt++) {
                int n = warpN * 32 + nt * 8 + gid;
                int kk = ks * 8 + tig;
                bfH[nt][0] = BsH[kk][n];     bfL[nt][0] = BsL[kk][n];
                bfH[nt][1] = BsH[kk + 4][n]; bfL[nt][1] = BsL[kk + 4][n];
            }
            #pragma unroll
            for (int mt = 0; mt < 2; mt++)
                #pragma unroll
                for (int nt = 0; nt < 4; nt++) {
                    MMA_TF32(acc[mt][nt], afH[mt][0], afH[mt][1], afH[mt][2], afH[mt][3],
                             bfL[nt][0], bfL[nt][1]);
                    MMA_TF32(acc[mt][nt], afL[mt][0], afL[mt][1], afL[mt][2], afL[mt][3],
                             bfH[nt][0], bfH[nt][1]);
                    MMA_TF32(acc[mt][nt], afH[mt][0], afH[mt][1], afH[mt][2], afH[mt][3],
                             bfH[nt][0], bfH[nt][1]);
                }
        }
        __syncthreads();
    }

    // epilogue
    #pragma unroll
    for (int mt = 0; mt < 2; mt++) {
        int r = row0 + warpM * 32 + mt * 16 + gid;
        #pragma unroll
        for (int nt = 0; nt < 4; nt++) {
            int c = col0 + warpN * 32 + nt * 8 + tig * 2;
            float* p0 = C + (size_t)r * N + c;
            float* p1 = C + (size_t)(r + 8) * N + c;
            if (accum) {
                p0[0] += acc[mt][nt][0]; p0[1] += acc[mt][nt][1];
                p1[0] += acc[mt][nt][2]; p1[1] += acc[mt][nt][3];
            } else {
                p0[0] = acc[mt][nt][0]; p0[1] = acc[mt][nt][1];
                p1[0] = acc[mt][nt][2]; p1[1] = acc[mt][nt][3];
            }
        }
    }
}

// ---------------- elementwise ----------------
__global__ void conv_silu_k(const float* __restrict__ x, const float* __restrict__ w,
                            float* __restrict__ y) {
    int i = blockIdx.x * blockDim.x + threadIdx.x;
    if (i >= T_ * D_) return;
    int t = i / D_, d = i % D_;
    float s = 0.f;
    #pragma unroll
    for (int j = 0; j < KC; j++) {
        int tt = t + j - (KC - 1);
        if (tt >= 0) s += x[tt*D_ + d] * w[d*KC + j];
    }
    y[i] = s / (1.f + expf(-s));
}

__global__ void l2norm_k(float* __restrict__ x) {
    int base = blockIdx.x * DK_;
    int tid = threadIdx.x;
    __shared__ float red[64];
    float v = x[base + tid];
    red[tid] = v * v; __syncthreads();
    for (int s = 32; s > 0; s >>= 1) {
        if (tid < s) red[tid] += red[tid + s];
        __syncthreads();
    }
    x[base + tid] = v * rsqrtf(red[0] + EPSF);
}

__global__ void headrms_k(float* __restrict__ x, const float* __restrict__ w) {
    int base = blockIdx.x * DK_;
    int tid = threadIdx.x;
    __shared__ float red[64];
    float v = x[base + tid];
    red[tid] = v * v; __syncthreads();
    for (int s = 32; s > 0; s >>= 1) {
        if (tid < s) red[tid] += red[tid + s];
        __syncthreads();
    }
    x[base + tid] = v * rsqrtf(red[0] / DK_ + EPSF) * w[tid];
}

__global__ void sigmoid_k(float* __restrict__ x, int n) {
    int i = blockIdx.x * blockDim.x + threadIdx.x;
    if (i < n) x[i] = 1.f / (1.f + expf(-x[i]));
}

__global__ void silu_mul_k(float* __restrict__ g, const float* __restrict__ u, int n) {
    int i = blockIdx.x * blockDim.x + threadIdx.x;
    if (i < n) { float v = g[i]; g[i] = (v / (1.f + expf(-v))) * u[i]; }
}

// ---------------- delta rule ----------------
// One block per head, 128 threads. Thread: vcol = tid>>1, rows (tid&1)*32..+31.
// Register prefetch of step t+1 during compute of t; 1 barrier/step.
__global__ void delta_k(const float* __restrict__ q, const float* __restrict__ k,
                        const float* __restrict__ v, const float* __restrict__ beta,
                        float* __restrict__ o) {
    int h = blockIdx.x;
    int tid = threadIdx.x;
    int vcol = tid >> 1, rbase = (tid & 1) * 32;
    float S[32];
    #pragma unroll
    for (int i = 0; i < 32; i++) S[i] = 0.f;
    __shared__ float ks[2][64], qs[2][64], vs[2][64], bsh[2];

    // preload step 0
    float rk = 0.f, rq = 0.f, rv = 0.f, rb = 0.f;
    {
        int off = h * DK_;
        if (tid < 64) { rk = k[off + tid]; rq = q[off + tid]; }
        else          { rv = v[off + tid - 64]; }
        if (tid == 127) rb = beta[h];
    }

    for (int t = 0; t < T_; t++) {
        int buf = t & 1;
        if (tid < 64) { ks[buf][tid] = rk; qs[buf][tid] = rq; }
        else          { vs[buf][tid - 64] = rv; }
        if (tid == 127) bsh[buf] = rb;
        __syncthreads();

        // prefetch step t+1 (lands while we compute step t)
        if (t + 1 < T_) {
            int off2 = ((t + 1) * H_ + h) * DK_;
            if (tid < 64) { rk = k[off2 + tid]; rq = q[off2 + tid]; }
            else          { rv = v[off2 + tid - 64]; }
            if (tid == 127) rb = beta[(t + 1) * H_ + h];
        }

        const float* kk = ks[buf];
        const float* qq = qs[buf];
        float a0 = 0.f, a1 = 0.f;
        #pragma unroll
        for (int i = 0; i < 32; i += 2) {
            a0 += kk[rbase+i]   * S[i];
            a1 += kk[rbase+i+1] * S[i+1];
        }
        float part = a0 + a1;
        float kS = part + __shfl_xor_sync(0xffffffffu, part, 1);
        float dl = bsh[buf] * (vs[buf][vcol] - kS);

        float o0 = 0.f, o1 = 0.f;
        #pragma unroll
        for (int i = 0; i < 32; i += 2) {
            S[i]   += kk[rbase+i]   * dl;  o0 += qq[rbase+i]   * S[i];
            S[i+1] += kk[rbase+i+1] * dl;  o1 += qq[rbase+i+1] * S[i+1];
        }
        float op = o0 + o1;
        float ov = op + __shfl_xor_sync(0xffffffffu, op, 1);
        int off = (t * H_ + h) * DK_;
        if ((tid & 1) == 0) o[off + vcol] = ov;
    }
}

__global__ void zero_loss_k() { g_loss = 0.f; g_cnt = 0.f; }

__global__ void loss_k(const float* __restrict__ logits, const int* __restrict__ tgt) {
    int t = blockIdx.x;
    const float* row = logits + (size_t)t * V_;
    __shared__ float red[256];
    float m = -1e30f;
    for (int i = threadIdx.x; i < V_; i += 256) m = fmaxf(m, row[i]);
    red[threadIdx.x] = m; __syncthreads();
    for (int s = 128; s > 0; s >>= 1) {
        if (threadIdx.x < s) red[threadIdx.x] = fmaxf(red[threadIdx.x], red[threadIdx.x+s]);
        __syncthreads();
    }
    m = red[0]; __syncthreads();
    float sum = 0.f;
    for (int i = threadIdx.x; i < V_; i += 256) sum += expf(row[i] - m);
    red[threadIdx.x] = sum; __syncthreads();
    for (int s = 128; s > 0; s >>= 1) {
        if (threadIdx.x < s) red[threadIdx.x] += red[threadIdx.x+s];
        __syncthreads();
    }
    if (threadIdx.x == 0) {
        int tg = tgt[t];
        if (tg >= 0) {
            int tc = tg < 0 ? 0 : (tg > V_-1 ? V_-1 : tg);
            float lse = m + logf(red[0]);
            atomicAdd(&g_loss, lse - row[tc]);
            atomicAdd(&g_cnt, 1.f);
        }
    }
}

__global__ void finalize_k(float* __restrict__ out, long long out_size) {
    float loss = g_loss / fmaxf(g_cnt, 1.f);
    const long long LG = (long long)T_ * V_;
    if (out_size == LG + 1) out[LG] = loss;
    else if (out_size < LG) out[0] = loss;
}

// ---------------- host side ----------------
static void run_gemm(int M, int N, int K, const float* A, const float* B, float* C, int accum) {
    if ((M % 64 == 0) && (N % 128 == 0) && (K % 16 == 0)) {
        dim3 grid(N / 128, M / 64);
        tf32gemm_k<<<grid, 256>>>(M, N, K, A, B, C, accum);
    } else {
        dim3 grid((N + 127) / 128, (M + 127) / 128);
        sgemm_k<<<grid, 256>>>(M, N, K, A, B, C, accum);
    }
}

extern "C" void kernel_launch(void* const* d_in, const int* in_sizes, int n_in,
                              void* d_out, int out_size) {
    const int*   idx        = (const int*)  d_in[0];
    const int*   targets    = (const int*)  d_in[1];
    const float* embed      = (const float*)d_in[2];
    const float* Wq         = (const float*)d_in[3];
    const float* Wk         = (const float*)d_in[4];
    const float* Wv         = (const float*)d_in[5];
    const float* conv_q     = (const float*)d_in[6];
    const float* conv_k     = (const float*)d_in[7];
    const float* conv_v     = (const float*)d_in[8];
    const float* Wb         = (const float*)d_in[9];
    const float* o_norm_w   = (const float*)d_in[10];
    const float* Wo         = (const float*)d_in[11];
    const float* attn_norm  = (const float*)d_in[12];
    const float* mlp_norm   = (const float*)d_in[13];
    const float* Wgate      = (const float*)d_in[14];
    const float* Wup        = (const float*)d_in[15];
    const float* Wdown      = (const float*)d_in[16];
    const float* final_norm = (const float*)d_in[17];
    const float* lm_head    = (const float*)d_in[18];

    float *h, *x, *qp, *kp, *vp, *q, *k, *v, *o, *y, *gate, *up, *beta, *lfb;
    cudaGetSymbolAddress((void**)&h,    g_h);
    cudaGetSymbolAddress((void**)&x,    g_x);
    cudaGetSymbolAddress((void**)&qp,   g_qp);
    cudaGetSymbolAddress((void**)&kp,   g_kp);
    cudaGetSymbolAddress((void**)&vp,   g_vp);
    cudaGetSymbolAddress((void**)&q,    g_q);
    cudaGetSymbolAddress((void**)&k,    g_k);
    cudaGetSymbolAddress((void**)&v,    g_v);
    cudaGetSymbolAddress((void**)&o,    g_o);
    cudaGetSymbolAddress((void**)&y,    g_y);
    cudaGetSymbolAddress((void**)&gate, g_gate);
    cudaGetSymbolAddress((void**)&up,   g_up);
    cudaGetSymbolAddress((void**)&beta, g_beta);
    cudaGetSymbolAddress((void**)&lfb,  g_logits_fb);

    const long long LG = (long long)T_ * V_;
    float* logits = ((long long)out_size >= LG) ? (float*)d_out : lfb;

    const int TD = T_ * D_;
    const int TF = T_ * FF_;

    embed_k<<<(TD + 255) / 256, 256>>>(idx, embed, h);

    for (int l = 0; l < L_; l++) {
        const float* Wq_l = Wq + (size_t)l * D_ * D_;
        const float* Wk_l = Wk + (size_t)l * D_ * D_;
        const float* Wv_l = Wv + (size_t)l * D_ * D_;
        const float* Wo_l = Wo + (size_t)l * D_ * D_;
        const float* Wb_l = Wb + (size_t)l * D_ * H_;
        const float* cq_l = conv_q + (size_t)l * D_ * KC;
        const float* ck_l = conv_k + (size_t)l * D_ * KC;
        const float* cv_l = conv_v + (size_t)l * D_ * KC;
        const float* Wg_l = Wgate + (size_t)l * D_ * FF_;
        const float* Wu_l = Wup   + (size_t)l * D_ * FF_;
        const float* Wd_l = Wdown + (size_t)l * FF_ * D_;

        rmsnorm_k<<<T_, 256>>>(h, attn_norm + (size_t)l * D_, x);

        run_gemm(T_, D_, D_, x, Wq_l, qp, 0);
        run_gemm(T_, D_, D_, x, Wk_l, kp, 0);
        run_gemm(T_, D_, D_, x, Wv_l, vp, 0);
        run_gemm(T_, H_, D_, x, Wb_l, beta, 0);
        sigmoid_k<<<(T_*H_ + 255) / 256, 256>>>(beta, T_*H_);

        conv_silu_k<<<(TD + 255) / 256, 256>>>(qp, cq_l, q);
        conv_silu_k<<<(TD + 255) / 256, 256>>>(kp, ck_l, k);
        conv_silu_k<<<(TD + 255) / 256, 256>>>(vp, cv_l, v);

        l2norm_k<<<T_*H_, 64>>>(q);
        l2norm_k<<<T_*H_, 64>>>(k);

        delta_k<<<H_, 128>>>(q, k, v, beta, o);

        headrms_k<<<T_*H_, 64>>>(o, o_norm_w + (size_t)l * DK_);

        run_gemm(T_, D_, D_, o, Wo_l, h, 1);

        rmsnorm_k<<<T_, 256>>>(h, mlp_norm + (size_t)l * D_, y);
        run_gemm(T_, FF_, D_, y, Wg_l, gate, 0);
        run_gemm(T_, FF_, D_, y, Wu_l, up, 0);
        silu_mul_k<<<(TF + 255) / 256, 256>>>(gate, up, TF);
        run_gemm(T_, D_, FF_, gate, Wd_l, h, 1);
    }

    rmsnorm_k<<<T_, 256>>>(h, final_norm, y);
    run_gemm(T_, V_, D_, y, lm_head, logits, 0);

    zero_loss_k<<<1, 1>>>();
    loss_k<<<T_, 256>>>(logits, targets);
    finalize_k<<<1, 1>>>((float*)d_out, (long long)out_size);
}

// round 8
// speedup vs baseline: 1.8468x; 1.1502x over previous
#include <cuda_runtime.h>
#include <stdint.h>
#include <math.h>

#define T_  2048
#define D_  768
#define L_  12
#define H_  12
#define DK_ 64
#define FF_ 2048
#define V_  50304
#define KC  4
#define EPSF 1e-6f

// ---------------- scratch (device globals; no runtime allocation) ----------------
__device__ float g_h  [T_*D_];
__device__ float g_x  [T_*D_];
__device__ float g_qp [T_*D_];
__device__ float g_kp [T_*D_];
__device__ float g_vp [T_*D_];
__device__ float g_q  [T_*D_];
__device__ float g_k  [T_*D_];
__device__ float g_v  [T_*D_];
__device__ float g_o  [T_*D_];
__device__ float g_y  [T_*D_];
__device__ float g_gate[T_*FF_];
__device__ float g_up  [T_*FF_];
__device__ float g_beta[T_*H_];
__device__ float g_loss, g_cnt;
__device__ float g_logits_fb[(size_t)T_*V_];

// ---------------- small kernels ----------------
__global__ void embed_k(const int* __restrict__ idx, const float* __restrict__ embed,
                        float* __restrict__ h) {
    int i = blockIdx.x * blockDim.x + threadIdx.x;
    if (i < T_ * D_) {
        int t = i / D_, d = i % D_;
        h[i] = embed[(size_t)idx[t] * D_ + d];
    }
}

__global__ void rmsnorm_k(const float* __restrict__ x, const float* __restrict__ w,
                          float* __restrict__ y) {
    int t = blockIdx.x;
    __shared__ float red[256];
    float ss = 0.f;
    for (int d = threadIdx.x; d < D_; d += 256) { float v = x[t*D_+d]; ss += v*v; }
    red[threadIdx.x] = ss; __syncthreads();
    for (int s = 128; s > 0; s >>= 1) {
        if (threadIdx.x < s) red[threadIdx.x] += red[threadIdx.x + s];
        __syncthreads();
    }
    float r = rsqrtf(red[0] / D_ + EPSF);
    for (int d = threadIdx.x; d < D_; d += 256) y[t*D_+d] = x[t*D_+d] * r * w[d];
}

// fallback fp32 SGEMM (only for tiny N, e.g. beta N=12)
__global__ void sgemm_k(int M, int N, int K,
                        const float* __restrict__ A, const float* __restrict__ B,
                        float* __restrict__ C, int accum) {
    __shared__ float As[8][128];
    __shared__ float Bs[8][128];
    int tid = threadIdx.x;
    int row0 = blockIdx.y * 128, col0 = blockIdx.x * 128;
    int ty = tid / 16, tx = tid % 16;
    float acc[8][8];
    #pragma unroll
    for (int i = 0; i < 8; i++)
        #pragma unroll
        for (int j = 0; j < 8; j++) acc[i][j] = 0.f;
    int aRow = tid >> 1, aK = (tid & 1) * 4;
    int bK = tid >> 5,  bCol = (tid & 31) * 4;
    for (int k0 = 0; k0 < K; k0 += 8) {
        #pragma unroll
        for (int i = 0; i < 4; i++) {
            int gr = row0 + aRow, gk = k0 + aK + i;
            As[aK + i][aRow] = (gr < M && gk < K) ? A[(size_t)gr * K + gk] : 0.f;
        }
        #pragma unroll
        for (int i = 0; i < 4; i++) {
            int gk = k0 + bK, gc = col0 + bCol + i;
            Bs[bK][bCol + i] = (gk < K && gc < N) ? B[(size_t)gk * N + gc] : 0.f;
        }
        __syncthreads();
        #pragma unroll
        for (int kk = 0; kk < 8; kk++) {
            float a[8], b[8];
            #pragma unroll
            for (int i = 0; i < 8; i++) a[i] = As[kk][ty*8 + i];
            #pragma unroll
            for (int j = 0; j < 8; j++) b[j] = Bs[kk][tx*8 + j];
            #pragma unroll
            for (int i = 0; i < 8; i++)
                #pragma unroll
                for (int j = 0; j < 8; j++) acc[i][j] += a[i] * b[j];
        }
        __syncthreads();
    }
    #pragma unroll
    for (int i = 0; i < 8; i++) {
        int r = row0 + ty*8 + i;
        if (r >= M) continue;
        #pragma unroll
        for (int j = 0; j < 8; j++) {
            int c = col0 + tx*8 + j;
            if (c < N) {
                size_t o = (size_t)r * N + c;
                C[o] = accum ? (C[o] + acc[i][j]) : acc[i][j];
            }
        }
    }
}

// ---------------- split-tf32 tensor-core GEMM with cp.async pipeline ----------
// C[M,N] = A[M,K] @ B[K,N] (+C). Requires M%64==0, N%128==0, K%16==0.
// Tile 64x128x16; 256 threads = 8 warps (2 x 4), warp tile 32x32.
// 3-stage cp.async pipeline, raw fp32 in smem, split in registers.
__device__ __forceinline__ unsigned int f2tf32(float f) {
    unsigned int r;
    asm("cvt.rna.tf32.f32 %0, %1;" : "=r"(r) : "f"(f));
    return r;
}
__device__ __forceinline__ void split_tf32(float f, unsigned int& hi, unsigned int& lo) {
    hi = f2tf32(f);
    lo = f2tf32(f - __uint_as_float(hi));
}
__device__ __forceinline__ void cp16(void* smem, const void* gmem) {
    unsigned int sa = (unsigned int)__cvta_generic_to_shared(smem);
    asm volatile("cp.async.ca.shared.global [%0], [%1], 16;" :: "r"(sa), "l"(gmem));
}
#define CP_COMMIT() asm volatile("cp.async.commit_group;")
#define CP_WAIT1()  asm volatile("cp.async.wait_group 1;")

#define MMA_TF32(acc, a0,a1,a2,a3, b0,b1)                                     \
    asm volatile(                                                             \
        "mma.sync.aligned.m16n8k8.row.col.f32.tf32.tf32.f32 "                 \
        "{%0,%1,%2,%3}, {%4,%5,%6,%7}, {%8,%9}, {%0,%1,%2,%3};\n"             \
        : "+f"(acc[0]), "+f"(acc[1]), "+f"(acc[2]), "+f"(acc[3])              \
        : "r"(a0), "r"(a1), "r"(a2), "r"(a3), "r"(b0), "r"(b1))

__device__ __forceinline__
void gemm_core(int M, int N, int K,
               const float* __restrict__ A, const float* __restrict__ B,
               float* __restrict__ C, int accum,
               int row0, int col0,
               float (*Asm)[64][20], float (*Bsm)[16][136]) {
    int tid = threadIdx.x;
    int lane = tid & 31, warp = tid >> 5;
    int warpM = warp & 1, warpN = warp >> 1;    // 2 x 4 warps
    int gid = lane >> 2, tig = lane & 3;

    float acc[2][4][4];
    #pragma unroll
    for (int mt = 0; mt < 2; mt++)
        #pragma unroll
        for (int nt = 0; nt < 4; nt++)
            #pragma unroll
            for (int i = 0; i < 4; i++) acc[mt][nt][i] = 0.f;

    int aRow = tid >> 2, aKq = (tid & 3) * 4;   // A: 64x16, 16B/thread
    int bK = tid >> 4, bNq = (tid & 15) * 8;    // B: 16x128, 32B/thread

    const float* aPtr = A + (size_t)(row0 + aRow) * K + aKq;
    const float* bPtr = B + (size_t)bK * N + col0 + bNq;

    int KT = K / 16;

    // prologue: issue stages 0 and 1
    #pragma unroll
    for (int s = 0; s < 2; s++) {
        if (s < KT) {
            cp16(&Asm[s][aRow][aKq], aPtr + s * 16);
            const float* bp = bPtr + (size_t)(s * 16) * N;
            cp16(&Bsm[s][bK][bNq], bp);
            cp16(&Bsm[s][bK][bNq + 4], bp + 4);
        }
        CP_COMMIT();
    }

    for (int kt = 0; kt < KT; kt++) {
        CP_WAIT1();          // stage kt landed
        __syncthreads();

        // issue stage kt+2 into buffer (kt+2)%3 (consumed at kt-1, safe now)
        {
            int s = kt + 2;
            int st2 = s % 3;
            if (s < KT) {
                cp16(&Asm[st2][aRow][aKq], aPtr + s * 16);
                const float* bp = bPtr + (size_t)(s * 16) * N;
                cp16(&Bsm[st2][bK][bNq], bp);
                cp16(&Bsm[st2][bK][bNq + 4], bp + 4);
            }
            CP_COMMIT();
        }

        int st = kt % 3;
        #pragma unroll
        for (int ks = 0; ks < 2; ks++) {
            unsigned int afH[2][4], afL[2][4];
            #pragma unroll
            for (int mt = 0; mt < 2; mt++) {
                int r = warpM * 32 + mt * 16 + gid;
                int c = ks * 8 + tig;
                split_tf32(Asm[st][r][c],         afH[mt][0], afL[mt][0]);
                split_tf32(Asm[st][r + 8][c],     afH[mt][1], afL[mt][1]);
                split_tf32(Asm[st][r][c + 4],     afH[mt][2], afL[mt][2]);
                split_tf32(Asm[st][r + 8][c + 4], afH[mt][3], afL[mt][3]);
            }
            unsigned int bfH[4][2], bfL[4][2];
            #pragma unroll
            for (int nt = 0; nt < 4; nt++) {
                int n = warpN * 32 + nt * 8 + gid;
                int kk = ks * 8 + tig;
                split_tf32(Bsm[st][kk][n],     bfH[nt][0], bfL[nt][0]);
                split_tf32(Bsm[st][kk + 4][n], bfH[nt][1], bfL[nt][1]);
            }
            #pragma unroll
            for (int mt = 0; mt < 2; mt++)
                #pragma unroll
                for (int nt = 0; nt < 4; nt++) {
                    MMA_TF32(acc[mt][nt], afH[mt][0], afH[mt][1], afH[mt][2], afH[mt][3],
                             bfL[nt][0], bfL[nt][1]);
                    MMA_TF32(acc[mt][nt], afL[mt][0], afL[mt][1], afL[mt][2], afL[mt][3],
                             bfH[nt][0], bfH[nt][1]);
                    MMA_TF32(acc[mt][nt], afH[mt][0], afH[mt][1], afH[mt][2], afH[mt][3],
                             bfH[nt][0], bfH[nt][1]);
                }
        }
        __syncthreads();
    }

    // epilogue
    #pragma unroll
    for (int mt = 0; mt < 2; mt++) {
        int r = row0 + warpM * 32 + mt * 16 + gid;
        #pragma unroll
        for (int nt = 0; nt < 4; nt++) {
            int c = col0 + warpN * 32 + nt * 8 + tig * 2;
            float* p0 = C + (size_t)r * N + c;
            float* p1 = C + (size_t)(r + 8) * N + c;
            if (accum) {
                p0[0] += acc[mt][nt][0]; p0[1] += acc[mt][nt][1];
                p1[0] += acc[mt][nt][2]; p1[1] += acc[mt][nt][3];
            } else {
                p0[0] = acc[mt][nt][0]; p0[1] = acc[mt][nt][1];
                p1[0] = acc[mt][nt][2]; p1[1] = acc[mt][nt][3];
            }
        }
    }
}

__global__ __launch_bounds__(256, 2)
void tf32gemm_k(int M, int N, int K,
                const float* __restrict__ A, const float* __restrict__ B,
                float* __restrict__ C, int accum) {
    __shared__ float Asm[3][64][20];
    __shared__ float Bsm[3][16][136];
    gemm_core(M, N, K, A, B, C, accum,
              blockIdx.y * 64, blockIdx.x * 128, Asm, Bsm);
}

// fused multi-matrix GEMM: z selects (B,C); same A. accum=0.
__global__ __launch_bounds__(256, 2)
void tf32gemm3_k(int M, int N, int K, const float* __restrict__ A,
                 const float* __restrict__ B0, const float* __restrict__ B1,
                 const float* __restrict__ B2,
                 float* __restrict__ C0, float* __restrict__ C1,
                 float* __restrict__ C2) {
    __shared__ float Asm[3][64][20];
    __shared__ float Bsm[3][16][136];
    const float* B = (blockIdx.z == 0) ? B0 : (blockIdx.z == 1) ? B1 : B2;
    float*       C = (blockIdx.z == 0) ? C0 : (blockIdx.z == 1) ? C1 : C2;
    gemm_core(M, N, K, A, B, C, 0,
              blockIdx.y * 64, blockIdx.x * 128, Asm, Bsm);
}

// ---------------- elementwise ----------------
__global__ void conv_silu_k(const float* __restrict__ x, const float* __restrict__ w,
                            float* __restrict__ y) {
    int i = blockIdx.x * blockDim.x + threadIdx.x;
    if (i >= T_ * D_) return;
    int t = i / D_, d = i % D_;
    float s = 0.f;
    #pragma unroll
    for (int j = 0; j < KC; j++) {
        int tt = t + j - (KC - 1);
        if (tt >= 0) s += x[tt*D_ + d] * w[d*KC + j];
    }
    y[i] = s / (1.f + expf(-s));
}

__global__ void l2norm_k(float* __restrict__ x) {
    int base = blockIdx.x * DK_;
    int tid = threadIdx.x;
    __shared__ float red[64];
    float v = x[base + tid];
    red[tid] = v * v; __syncthreads();
    for (int s = 32; s > 0; s >>= 1) {
        if (tid < s) red[tid] += red[tid + s];
        __syncthreads();
    }
    x[base + tid] = v * rsqrtf(red[0] + EPSF);
}

__global__ void headrms_k(float* __restrict__ x, const float* __restrict__ w) {
    int base = blockIdx.x * DK_;
    int tid = threadIdx.x;
    __shared__ float red[64];
    float v = x[base + tid];
    red[tid] = v * v; __syncthreads();
    for (int s = 32; s > 0; s >>= 1) {
        if (tid < s) red[tid] += red[tid + s];
        __syncthreads();
    }
    x[base + tid] = v * rsqrtf(red[0] / DK_ + EPSF) * w[tid];
}

__global__ void sigmoid_k(float* __restrict__ x, int n) {
    int i = blockIdx.x * blockDim.x + threadIdx.x;
    if (i < n) x[i] = 1.f / (1.f + expf(-x[i]));
}

__global__ void silu_mul_k(float* __restrict__ g, const float* __restrict__ u, int n) {
    int i = blockIdx.x * blockDim.x + threadIdx.x;
    if (i < n) { float v = g[i]; g[i] = (v / (1.f + expf(-v))) * u[i]; }
}

// ---------------- delta rule ----------------
__global__ void delta_k(const float* __restrict__ q, const float* __restrict__ k,
                        const float* __restrict__ v, const float* __restrict__ beta,
                        float* __restrict__ o) {
    int h = blockIdx.x;
    int tid = threadIdx.x;
    int vcol = tid >> 1, rbase = (tid & 1) * 32;
    float S[32];
    #pragma unroll
    for (int i = 0; i < 32; i++) S[i] = 0.f;
    __shared__ float ks[2][64], qs[2][64], vs[2][64], bsh[2];

    float rk = 0.f, rq = 0.f, rv = 0.f, rb = 0.f;
    {
        int off = h * DK_;
        if (tid < 64) { rk = k[off + tid]; rq = q[off + tid]; }
        else          { rv = v[off + tid - 64]; }
        if (tid == 127) rb = beta[h];
    }

    for (int t = 0; t < T_; t++) {
        int buf = t & 1;
        if (tid < 64) { ks[buf][tid] = rk; qs[buf][tid] = rq; }
        else          { vs[buf][tid - 64] = rv; }
        if (tid == 127) bsh[buf] = rb;
        __syncthreads();

        if (t + 1 < T_) {
            int off2 = ((t + 1) * H_ + h) * DK_;
            if (tid < 64) { rk = k[off2 + tid]; rq = q[off2 + tid]; }
            else          { rv = v[off2 + tid - 64]; }
            if (tid == 127) rb = beta[(t + 1) * H_ + h];
        }

        const float* kk = ks[buf];
        const float* qq = qs[buf];
        float a0 = 0.f, a1 = 0.f;
        #pragma unroll
        for (int i = 0; i < 32; i += 2) {
            a0 += kk[rbase+i]   * S[i];
            a1 += kk[rbase+i+1] * S[i+1];
        }
        float part = a0 + a1;
        float kS = part + __shfl_xor_sync(0xffffffffu, part, 1);
        float dl = bsh[buf] * (vs[buf][vcol] - kS);

        float o0 = 0.f, o1 = 0.f;
        #pragma unroll
        for (int i = 0; i < 32; i += 2) {
            S[i]   += kk[rbase+i]   * dl;  o0 += qq[rbase+i]   * S[i];
            S[i+1] += kk[rbase+i+1] * dl;  o1 += qq[rbase+i+1] * S[i+1];
        }
        float op = o0 + o1;
        float ov = op + __shfl_xor_sync(0xffffffffu, op, 1);
        int off = (t * H_ + h) * DK_;
        if ((tid & 1) == 0) o[off + vcol] = ov;
    }
}

__global__ void zero_loss_k() { g_loss = 0.f; g_cnt = 0.f; }

__global__ void loss_k(const float* __restrict__ logits, const int* __restrict__ tgt) {
    int t = blockIdx.x;
    const float* row = logits + (size_t)t * V_;
    __shared__ float red[256];
    float m = -1e30f;
    for (int i = threadIdx.x; i < V_; i += 256) m = fmaxf(m, row[i]);
    red[threadIdx.x] = m; __syncthreads();
    for (int s = 128; s > 0; s >>= 1) {
        if (threadIdx.x < s) red[threadIdx.x] = fmaxf(red[threadIdx.x], red[threadIdx.x+s]);
        __syncthreads();
    }
    m = red[0]; __syncthreads();
    float sum = 0.f;
    for (int i = threadIdx.x; i < V_; i += 256) sum += expf(row[i] - m);
    red[threadIdx.x] = sum; __syncthreads();
    for (int s = 128; s > 0; s >>= 1) {
        if (threadIdx.x < s) red[threadIdx.x] += red[threadIdx.x+s];
        __syncthreads();
    }
    if (threadIdx.x == 0) {
        int tg = tgt[t];
        if (tg >= 0) {
            int tc = tg < 0 ? 0 : (tg > V_-1 ? V_-1 : tg);
            float lse = m + logf(red[0]);
            atomicAdd(&g_loss, lse - row[tc]);
            atomicAdd(&g_cnt, 1.f);
        }
    }
}

__global__ void finalize_k(float* __restrict__ out, long long out_size) {
    float loss = g_loss / fmaxf(g_cnt, 1.f);
    const long long LG = (long long)T_ * V_;
    if (out_size == LG + 1) out[LG] = loss;
    else if (out_size < LG) out[0] = loss;
}

// ---------------- host side ----------------
static void run_gemm(int M, int N, int K, const float* A, const float* B, float* C, int accum) {
    if ((M % 64 == 0) && (N % 128 == 0) && (K % 16 == 0)) {
        dim3 grid(N / 128, M / 64);
        tf32gemm_k<<<grid, 256>>>(M, N, K, A, B, C, accum);
    } else {
        dim3 grid((N + 127) / 128, (M + 127) / 128);
        sgemm_k<<<grid, 256>>>(M, N, K, A, B, C, accum);
    }
}

static void run_gemm_multi(int M, int N, int K, const float* A,
                           const float* B0, const float* B1, const float* B2,
                           float* C0, float* C1, float* C2, int nmat) {
    dim3 grid(N / 128, M / 64, nmat);
    tf32gemm3_k<<<grid, 256>>>(M, N, K, A, B0, B1, B2, C0, C1, C2);
}

extern "C" void kernel_launch(void* const* d_in, const int* in_sizes, int n_in,
                              void* d_out, int out_size) {
    const int*   idx        = (const int*)  d_in[0];
    const int*   targets    = (const int*)  d_in[1];
    const float* embed      = (const float*)d_in[2];
    const float* Wq         = (const float*)d_in[3];
    const float* Wk         = (const float*)d_in[4];
    const float* Wv         = (const float*)d_in[5];
    const float* conv_q     = (const float*)d_in[6];
    const float* conv_k     = (const float*)d_in[7];
    const float* conv_v     = (const float*)d_in[8];
    const float* Wb         = (const float*)d_in[9];
    const float* o_norm_w   = (const float*)d_in[10];
    const float* Wo         = (const float*)d_in[11];
    const float* attn_norm  = (const float*)d_in[12];
    const float* mlp_norm   = (const float*)d_in[13];
    const float* Wgate      = (const float*)d_in[14];
    const float* Wup        = (const float*)d_in[15];
    const float* Wdown      = (const float*)d_in[16];
    const float* final_norm = (const float*)d_in[17];
    const float* lm_head    = (const float*)d_in[18];

    float *h, *x, *qp, *kp, *vp, *q, *k, *v, *o, *y, *gate, *up, *beta, *lfb;
    cudaGetSymbolAddress((void**)&h,    g_h);
    cudaGetSymbolAddress((void**)&x,    g_x);
    cudaGetSymbolAddress((void**)&qp,   g_qp);
    cudaGetSymbolAddress((void**)&kp,   g_kp);
    cudaGetSymbolAddress((void**)&vp,   g_vp);
    cudaGetSymbolAddress((void**)&q,    g_q);
    cudaGetSymbolAddress((void**)&k,    g_k);
    cudaGetSymbolAddress((void**)&v,    g_v);
    cudaGetSymbolAddress((void**)&o,    g_o);
    cudaGetSymbolAddress((void**)&y,    g_y);
    cudaGetSymbolAddress((void**)&gate, g_gate);
    cudaGetSymbolAddress((void**)&up,   g_up);
    cudaGetSymbolAddress((void**)&beta, g_beta);
    cudaGetSymbolAddress((void**)&lfb,  g_logits_fb);

    const long long LG = (long long)T_ * V_;
    float* logits = ((long long)out_size >= LG) ? (float*)d_out : lfb;

    const int TD = T_ * D_;
    const int TF = T_ * FF_;

    embed_k<<<(TD + 255) / 256, 256>>>(idx, embed, h);

    for (int l = 0; l < L_; l++) {
        const float* Wq_l = Wq + (size_t)l * D_ * D_;
        const float* Wk_l = Wk + (size_t)l * D_ * D_;
        const float* Wv_l = Wv + (size_t)l * D_ * D_;
        const float* Wo_l = Wo + (size_t)l * D_ * D_;
        const float* Wb_l = Wb + (size_t)l * D_ * H_;
        const float* cq_l = conv_q + (size_t)l * D_ * KC;
        const float* ck_l = conv_k + (size_t)l * D_ * KC;
        const float* cv_l = conv_v + (size_t)l * D_ * KC;
        const float* Wg_l = Wgate + (size_t)l * D_ * FF_;
        const float* Wu_l = Wup   + (size_t)l * D_ * FF_;
        const float* Wd_l = Wdown + (size_t)l * FF_ * D_;

        rmsnorm_k<<<T_, 256>>>(h, attn_norm + (size_t)l * D_, x);

        // fused q/k/v projections (one launch, 576 CTAs)
        run_gemm_multi(T_, D_, D_, x, Wq_l, Wk_l, Wv_l, qp, kp, vp, 3);
        run_gemm(T_, H_, D_, x, Wb_l, beta, 0);
        sigmoid_k<<<(T_*H_ + 255) / 256, 256>>>(beta, T_*H_);

        conv_silu_k<<<(TD + 255) / 256, 256>>>(qp, cq_l, q);
        conv_silu_k<<<(TD + 255) / 256, 256>>>(kp, ck_l, k);
        conv_silu_k<<<(TD + 255) / 256, 256>>>(vp, cv_l, v);

        l2norm_k<<<T_*H_, 64>>>(q);
        l2norm_k<<<T_*H_, 64>>>(k);

        delta_k<<<H_, 128>>>(q, k, v, beta, o);

        headrms_k<<<T_*H_, 64>>>(o, o_norm_w + (size_t)l * DK_);

        run_gemm(T_, D_, D_, o, Wo_l, h, 1);

        rmsnorm_k<<<T_, 256>>>(h, mlp_norm + (size_t)l * D_, y);
        // fused gate/up (one launch, 384 CTAs)
        run_gemm_multi(T_, FF_, D_, y, Wg_l, Wu_l, Wu_l, gate, up, up, 2);
        silu_mul_k<<<(TF + 255) / 256, 256>>>(gate, up, TF);
        run_gemm(T_, D_, FF_, gate, Wd_l, h, 1);
    }

    rmsnorm_k<<<T_, 256>>>(h, final_norm, y);
    run_gemm(T_, V_, D_, y, lm_head, logits, 0);

    zero_loss_k<<<1, 1>>>();
    loss_k<<<T_, 256>>>(logits, targets);
    finalize_k<<<1, 1>>>((float*)d_out, (long long)out_size);
}